// round 2
// baseline (speedup 1.0000x reference)
#include <cuda_runtime.h>
#include <math.h>

#define NN 32768
#define EE 327680
#define GG 64
#define IND 771
#define HH 256
#define LL 4

// ---------------- scratch (static device globals; no allocation) ------------
__device__ float g_h[NN * HH];
__device__ float g_q[NN * HH];
__device__ float g_k[NN * HH];
__device__ float g_v[NN * HH];
__device__ float g_xr[NN * HH];
__device__ float g_att[NN * HH];
__device__ int   g_cnt[NN];
__device__ int   g_rowptr[NN + 1];
__device__ int   g_cursor[NN];
__device__ int   g_eids[EE];
__device__ float g_Me[4 * HH];
__device__ float g_be[HH];
__device__ float g_wbo[HH];
__device__ float g_wbx[HH];

// ---------------- CSR build ------------------------------------------------
__global__ void zero_cnt_kernel() {
    int i = blockIdx.x * blockDim.x + threadIdx.x;
    g_cnt[i] = 0;
}

__global__ void hist_kernel(const int* __restrict__ dst) {
    int e = blockIdx.x * blockDim.x + threadIdx.x;
    atomicAdd(&g_cnt[dst[e]], 1);
}

__global__ void scan_kernel() {
    // 1024 threads, each handles 32 elements (N = 32768 exactly)
    __shared__ int ssum[1024];
    int t = threadIdx.x;
    int base = t * 32;
    int local[32];
    int s = 0;
#pragma unroll
    for (int i = 0; i < 32; i++) { local[i] = s; s += g_cnt[base + i]; }
    ssum[t] = s;
    __syncthreads();
    // Hillis-Steele inclusive scan
    for (int off = 1; off < 1024; off <<= 1) {
        int v = (t >= off) ? ssum[t - off] : 0;
        __syncthreads();
        ssum[t] += v;
        __syncthreads();
    }
    int offBase = (t == 0) ? 0 : ssum[t - 1];
#pragma unroll
    for (int i = 0; i < 32; i++) g_rowptr[base + i] = offBase + local[i];
    if (t == 1023) g_rowptr[NN] = offBase + s;
}

__global__ void init_cursor_kernel() {
    int i = blockIdx.x * blockDim.x + threadIdx.x;
    g_cursor[i] = g_rowptr[i];
}

__global__ void fill_kernel(const int* __restrict__ dst) {
    int e = blockIdx.x * blockDim.x + threadIdx.x;
    int p = atomicAdd(&g_cursor[dst[e]], 1);
    g_eids[p] = e;
}

// deterministic ordering: sort each node's incoming-edge list by edge id
__global__ void sort_kernel() {
    int n = blockIdx.x * blockDim.x + threadIdx.x;
    int lo = g_rowptr[n], hi = g_rowptr[n + 1];
    for (int i = lo + 1; i < hi; i++) {
        int key = g_eids[i];
        int j = i - 1;
        while (j >= lo && g_eids[j] > key) { g_eids[j + 1] = g_eids[j]; j--; }
        g_eids[j + 1] = key;
    }
}

// ---------------- per-layer precompute ------------------------------------
// Me[a][j] = sum_c W_ep[a,c] * We[c,j]   (rank-4 factorization of edge proj)
// be[j]    = sum_c b_ep[c]  * We[c,j]
// wbo/wbx: folded Wbeta for concat([out, xr, out-xr]) @ Wbeta
__global__ void prep_layer_kernel(const float* __restrict__ W_ep,
                                  const float* __restrict__ b_ep,
                                  const float* __restrict__ We,
                                  const float* __restrict__ Wbeta) {
    int j = threadIdx.x;
    float m0 = 0.f, m1 = 0.f, m2 = 0.f, m3 = 0.f, bb = 0.f;
    for (int c = 0; c < HH; c++) {
        float w = We[c * HH + j];
        m0 += W_ep[c] * w;
        m1 += W_ep[HH + c] * w;
        m2 += W_ep[2 * HH + c] * w;
        m3 += W_ep[3 * HH + c] * w;
        bb += b_ep[c] * w;
    }
    g_Me[j] = m0; g_Me[HH + j] = m1; g_Me[2 * HH + j] = m2; g_Me[3 * HH + j] = m3;
    g_be[j] = bb;
    g_wbo[j] = Wbeta[j] + Wbeta[2 * HH + j];
    g_wbx[j] = Wbeta[HH + j] - Wbeta[2 * HH + j];
}

// ---------------- SGEMM core: 128x128 tile, 8x8 per thread -----------------
__device__ __forceinline__ void sgemm_tile(const float* __restrict__ A,
                                           const float* __restrict__ B,
                                           const float* __restrict__ bias,
                                           float* __restrict__ C, int K,
                                           int rowBase, int colBase) {
    __shared__ float As[8][132];   // padded: conflict-free, 16B-aligned rows
    __shared__ float Bs[8][128];
    int tid = threadIdx.x;
    int tx = tid & 15, ty = tid >> 4;
    float acc[8][8];
#pragma unroll
    for (int i = 0; i < 8; i++)
#pragma unroll
        for (int j = 0; j < 8; j++) acc[i][j] = 0.f;

    for (int k0 = 0; k0 < K; k0 += 8) {
#pragma unroll
        for (int i = 0; i < 4; i++) {
            int idx = i * 256 + tid;
            int r = idx >> 3, c = idx & 7;
            int kk = k0 + c;
            As[c][r] = (kk < K) ? A[(size_t)(rowBase + r) * K + kk] : 0.f;
        }
#pragma unroll
        for (int i = 0; i < 4; i++) {
            int idx = i * 256 + tid;
            int kk = idx >> 7, c = idx & 127;
            Bs[kk][c] = (k0 + kk < K) ? B[(size_t)(k0 + kk) * 256 + colBase + c] : 0.f;
        }
        __syncthreads();
#pragma unroll
        for (int kk = 0; kk < 8; kk++) {
            float ra[8], rb[8];
#pragma unroll
            for (int m = 0; m < 8; m++) ra[m] = As[kk][ty * 8 + m];
#pragma unroll
            for (int n = 0; n < 8; n++) rb[n] = Bs[kk][tx * 8 + n];
#pragma unroll
            for (int m = 0; m < 8; m++)
#pragma unroll
                for (int n = 0; n < 8; n++) acc[m][n] += ra[m] * rb[n];
        }
        __syncthreads();
    }
#pragma unroll
    for (int m = 0; m < 8; m++) {
        int row = rowBase + ty * 8 + m;
        int col = colBase + tx * 8;
        float4 r0 = make_float4(acc[m][0] + bias[col + 0], acc[m][1] + bias[col + 1],
                                acc[m][2] + bias[col + 2], acc[m][3] + bias[col + 3]);
        float4 r1 = make_float4(acc[m][4] + bias[col + 4], acc[m][5] + bias[col + 5],
                                acc[m][6] + bias[col + 6], acc[m][7] + bias[col + 7]);
        float4* cp = (float4*)(C + (size_t)row * 256 + col);
        cp[0] = r0; cp[1] = r1;
    }
}

// input projection: h = x @ W_in + b_in
__global__ void __launch_bounds__(256)
sgemm_in_kernel(const float* __restrict__ A, const float* __restrict__ B,
                const float* __restrict__ bias) {
    sgemm_tile(A, B, bias, g_h, IND, blockIdx.y * 128, blockIdx.x * 128);
}

// fused Q/K/V/skip projections: blockIdx.z selects which of the four GEMMs
__global__ void __launch_bounds__(256)
sgemm_qkvs_kernel(const float* __restrict__ Wq, const float* __restrict__ bq,
                  const float* __restrict__ Wk, const float* __restrict__ bk,
                  const float* __restrict__ Wv, const float* __restrict__ bv,
                  const float* __restrict__ Ws, const float* __restrict__ bs) {
    const float* B; const float* bias; float* C;
    switch (blockIdx.z) {
        case 0:  B = Wq; bias = bq; C = g_q;  break;
        case 1:  B = Wk; bias = bk; C = g_k;  break;
        case 2:  B = Wv; bias = bv; C = g_v;  break;
        default: B = Ws; bias = bs; C = g_xr; break;
    }
    sgemm_tile(g_h, B, bias, C, HH, blockIdx.y * 128, blockIdx.x * 128);
}

// ---------------- attention: warp per node, online softmax ----------------
// lane l owns dims [8l, 8l+8); head = l/4; dot reduced over 4-lane groups
__global__ void __launch_bounds__(128)
attn_kernel(const float* __restrict__ eattr, const int* __restrict__ src) {
    __shared__ float sMe[4 * HH];
    __shared__ float sbe[HH];
    for (int i = threadIdx.x; i < 4 * HH; i += 128) sMe[i] = g_Me[i];
    for (int i = threadIdx.x; i < HH; i += 128) sbe[i] = g_be[i];
    __syncthreads();

    int n = blockIdx.x * 4 + (threadIdx.x >> 5);
    int lane = threadIdx.x & 31;
    int dim0 = lane * 8;

    const float4* q4 = (const float4*)(g_q + (size_t)n * HH + dim0);
    float4 qa = q4[0], qb = q4[1];
    float ql[8] = {qa.x, qa.y, qa.z, qa.w, qb.x, qb.y, qb.z, qb.w};

    float m = -INFINITY, lsum = 0.f;
    float acc[8] = {0.f, 0.f, 0.f, 0.f, 0.f, 0.f, 0.f, 0.f};

    int e0 = g_rowptr[n], e1 = g_rowptr[n + 1];
    for (int ii = e0; ii < e1; ii++) {
        int eid = g_eids[ii];
        int s = src[eid];
        float a0 = eattr[eid * 4 + 0], a1 = eattr[eid * 4 + 1];
        float a2 = eattr[eid * 4 + 2], a3 = eattr[eid * 4 + 3];
        float ed[8];
#pragma unroll
        for (int d = 0; d < 8; d++) {
            int dd = dim0 + d;
            ed[d] = sbe[dd] + a0 * sMe[dd] + a1 * sMe[HH + dd]
                            + a2 * sMe[2 * HH + dd] + a3 * sMe[3 * HH + dd];
        }
        const float4* k4 = (const float4*)(g_k + (size_t)s * HH + dim0);
        float4 ka = k4[0], kb = k4[1];
        float kj[8] = {ka.x, ka.y, ka.z, ka.w, kb.x, kb.y, kb.z, kb.w};
        float part = 0.f;
#pragma unroll
        for (int d = 0; d < 8; d++) part += ql[d] * (kj[d] + ed[d]);
        part += __shfl_xor_sync(0xffffffffu, part, 1);
        part += __shfl_xor_sync(0xffffffffu, part, 2);
        float alpha = part * 0.17677669529663687f;  // 1/sqrt(32)

        float mnew = fmaxf(m, alpha);
        float scale = __expf(m - mnew);   // m==-inf on first edge -> 0
        float w = __expf(alpha - mnew);
        lsum = lsum * scale + w;

        const float4* v4 = (const float4*)(g_v + (size_t)s * HH + dim0);
        float4 va = v4[0], vb = v4[1];
        float vj[8] = {va.x, va.y, va.z, va.w, vb.x, vb.y, vb.z, vb.w};
#pragma unroll
        for (int d = 0; d < 8; d++) acc[d] = acc[d] * scale + w * (vj[d] + ed[d]);
        m = mnew;
    }
    float inv = 1.f / (lsum + 1e-16f);
    float4* o = (float4*)(g_att + (size_t)n * HH + dim0);
    o[0] = make_float4(acc[0] * inv, acc[1] * inv, acc[2] * inv, acc[3] * inv);
    o[1] = make_float4(acc[4] * inv, acc[5] * inv, acc[6] * inv, acc[7] * inv);
}

// ---------------- fused beta-gate + LayerNorm + ReLU + residual ------------
__device__ __forceinline__ float warpSum(float x) {
    x += __shfl_xor_sync(0xffffffffu, x, 16);
    x += __shfl_xor_sync(0xffffffffu, x, 8);
    x += __shfl_xor_sync(0xffffffffu, x, 4);
    x += __shfl_xor_sync(0xffffffffu, x, 2);
    x += __shfl_xor_sync(0xffffffffu, x, 1);
    return x;
}

__global__ void __launch_bounds__(128)
fuse_kernel(const float* __restrict__ lng, const float* __restrict__ lnb) {
    int n = blockIdx.x * 4 + (threadIdx.x >> 5);
    int lane = threadIdx.x & 31;
    int dim0 = lane * 8;
    size_t base = (size_t)n * HH + dim0;

    const float4* o4 = (const float4*)(g_att + base);
    const float4* x4 = (const float4*)(g_xr + base);
    float4 oa = o4[0], ob = o4[1], xa = x4[0], xb = x4[1];
    float o[8] = {oa.x, oa.y, oa.z, oa.w, ob.x, ob.y, ob.z, ob.w};
    float xr[8] = {xa.x, xa.y, xa.z, xa.w, xb.x, xb.y, xb.z, xb.w};

    float part = 0.f;
#pragma unroll
    for (int d = 0; d < 8; d++)
        part += o[d] * g_wbo[dim0 + d] + xr[d] * g_wbx[dim0 + d];
    part = warpSum(part);
    float beta = 1.f / (1.f + __expf(-part));

    float hn[8];
    float ssum = 0.f;
#pragma unroll
    for (int d = 0; d < 8; d++) { hn[d] = beta * xr[d] + (1.f - beta) * o[d]; ssum += hn[d]; }
    float mu = warpSum(ssum) * (1.f / HH);
    float sv = 0.f;
#pragma unroll
    for (int d = 0; d < 8; d++) { float t = hn[d] - mu; sv += t * t; }
    float var = warpSum(sv) * (1.f / HH);
    float inv = rsqrtf(var + 1e-5f);
#pragma unroll
    for (int d = 0; d < 8; d++) {
        float y = (hn[d] - mu) * inv * lng[dim0 + d] + lnb[dim0 + d];
        g_h[base + d] = fmaxf(y, 0.f) + g_h[base + d];   // + residual (old h)
    }
}

// ---------------- pooling + 3-layer head (block per graph) -----------------
__global__ void __launch_bounds__(256)
pool_head_kernel(const int* __restrict__ batch,
                 const float* __restrict__ Wc1, const float* __restrict__ bc1,
                 const float* __restrict__ lncg, const float* __restrict__ lncb,
                 const float* __restrict__ Wc2, const float* __restrict__ bc2,
                 const float* __restrict__ Wc3, const float* __restrict__ bc3,
                 float* __restrict__ out) {
    int g = blockIdx.x, tid = threadIdx.x;
    __shared__ int s_lo, s_hi;
    if (tid == 0) {
        int lo = 0, hi = NN;
        while (lo < hi) { int mid = (lo + hi) >> 1; if (batch[mid] < g) lo = mid + 1; else hi = mid; }
        s_lo = lo;
        lo = 0; hi = NN;
        while (lo < hi) { int mid = (lo + hi) >> 1; if (batch[mid] < g + 1) lo = mid + 1; else hi = mid; }
        s_hi = lo;
    }
    __syncthreads();
    int lo = s_lo, hi = s_hi;
    float sum = 0.f;
    for (int n = lo; n < hi; n++) sum += g_h[(size_t)n * HH + tid];
    __shared__ float ge[2 * HH];
    float cnt = (float)((hi - lo) > 1 ? (hi - lo) : 1);
    ge[tid] = sum / cnt;
    ge[HH + tid] = sum;
    __syncthreads();

    float c1 = bc1[tid];
    for (int k = 0; k < 2 * HH; k++) c1 += ge[k] * Wc1[k * HH + tid];

    __shared__ float red[HH];
    red[tid] = c1; __syncthreads();
    for (int s = HH / 2; s > 0; s >>= 1) { if (tid < s) red[tid] += red[tid + s]; __syncthreads(); }
    float mu = red[0] * (1.f / HH);
    __syncthreads();
    float t = c1 - mu;
    red[tid] = t * t; __syncthreads();
    for (int s = HH / 2; s > 0; s >>= 1) { if (tid < s) red[tid] += red[tid + s]; __syncthreads(); }
    float var = red[0] * (1.f / HH);
    __syncthreads();
    float y = (c1 - mu) * rsqrtf(var + 1e-5f) * lncg[tid] + lncb[tid];
    float c1r = fmaxf(y, 0.f);

    __shared__ float s1[HH];
    s1[tid] = c1r; __syncthreads();
    __shared__ float s2[HH / 2];
    if (tid < HH / 2) {
        float c2 = bc2[tid];
        for (int k = 0; k < HH; k++) c2 += s1[k] * Wc2[k * (HH / 2) + tid];
        s2[tid] = fmaxf(c2, 0.f);
    }
    __syncthreads();
    if (tid < HH / 2) red[tid] = s2[tid] * Wc3[tid];
    __syncthreads();
    for (int s = HH / 4; s > 0; s >>= 1) { if (tid < s) red[tid] += red[tid + s]; __syncthreads(); }
    if (tid == 0) out[g] = red[0] + bc3[0];
}

// ---------------- host launcher -------------------------------------------
extern "C" void kernel_launch(void* const* d_in, const int* in_sizes, int n_in,
                              void* d_out_, int out_size) {
    const float* x     = (const float*)d_in[0];
    const int*   ei    = (const int*)  d_in[1];
    const float* eattr = (const float*)d_in[2];
    const int*   batch = (const int*)  d_in[3];
    const float* W_in  = (const float*)d_in[4];
    const float* b_in  = (const float*)d_in[5];
    const float* W_ep  = (const float*)d_in[6];
    const float* b_ep  = (const float*)d_in[7];
    const float* Wq    = (const float*)d_in[8];
    const float* bq    = (const float*)d_in[9];
    const float* Wk    = (const float*)d_in[10];
    const float* bk    = (const float*)d_in[11];
    const float* Wv    = (const float*)d_in[12];
    const float* bv    = (const float*)d_in[13];
    const float* We    = (const float*)d_in[14];
    const float* Wskip = (const float*)d_in[15];
    const float* bskip = (const float*)d_in[16];
    const float* Wbeta = (const float*)d_in[17];
    const float* lng   = (const float*)d_in[18];
    const float* lnb   = (const float*)d_in[19];
    const float* Wc1   = (const float*)d_in[20];
    const float* bc1   = (const float*)d_in[21];
    const float* lncg  = (const float*)d_in[22];
    const float* lncb  = (const float*)d_in[23];
    const float* Wc2   = (const float*)d_in[24];
    const float* bc2   = (const float*)d_in[25];
    const float* Wc3   = (const float*)d_in[26];
    const float* bc3   = (const float*)d_in[27];
    float* out = (float*)d_out_;

    const int* src = ei;        // edge_index[0]
    const int* dst = ei + EE;   // edge_index[1]

    // CSR build (deterministic after per-node sort)
    zero_cnt_kernel<<<NN / 256, 256>>>();
    hist_kernel<<<EE / 256, 256>>>(dst);
    scan_kernel<<<1, 1024>>>();
    init_cursor_kernel<<<NN / 256, 256>>>();
    fill_kernel<<<EE / 256, 256>>>(dst);
    sort_kernel<<<NN / 256, 256>>>();

    // input projection
    sgemm_in_kernel<<<dim3(2, 256), 256>>>(x, W_in, b_in);

    for (int i = 0; i < LL; i++) {
        prep_layer_kernel<<<1, HH>>>(W_ep, b_ep, We + i * HH * HH, Wbeta + i * 3 * HH);
        sgemm_qkvs_kernel<<<dim3(2, 256, 4), 256>>>(
            Wq + i * HH * HH, bq + i * HH,
            Wk + i * HH * HH, bk + i * HH,
            Wv + i * HH * HH, bv + i * HH,
            Wskip + i * HH * HH, bskip + i * HH);
        attn_kernel<<<NN / 4, 128>>>(eattr, src);
        fuse_kernel<<<NN / 4, 128>>>(lng + i * HH, lnb + i * HH);
    }

    pool_head_kernel<<<GG, 256>>>(batch, Wc1, bc1, lncg, lncb, Wc2, bc2, Wc3, bc3, out);
}

// round 4
// speedup vs baseline: 1.3853x; 1.3853x over previous
#include <cuda_runtime.h>
#include <cuda_bf16.h>
#include <math.h>
#include <stdint.h>

#define NN 32768
#define EE 327680
#define GG 64
#define IND 771
#define KPAD_IN 896          /* 771 zero-padded to 28 chunks of 32 */
#define HH 256
#define LL 4

// ===================== scratch (static device globals) ======================
__device__ float g_h[NN * HH];
__device__ float g_q[NN * HH];
__device__ float g_k[NN * HH];
__device__ float g_v[NN * HH];
__device__ float g_xr[NN * HH];
__device__ float g_att[NN * HH];
__device__ int   g_cnt[NN];
__device__ int   g_rowptr[NN + 1];
__device__ int   g_cursor[NN];
__device__ int   g_eids[EE];
__device__ float g_Me[4 * HH];
__device__ float g_be[HH];
__device__ float g_wbo[HH];
__device__ float g_wbx[HH];
// bf16 split operands for tensor-core GEMMs
__device__ __nv_bfloat16 g_xh[NN * KPAD_IN];
__device__ __nv_bfloat16 g_xl[NN * KPAD_IN];
__device__ __nv_bfloat16 g_hh[NN * HH];
__device__ __nv_bfloat16 g_hl[NN * HH];
__device__ __nv_bfloat16 g_wth_in[HH * KPAD_IN];
__device__ __nv_bfloat16 g_wtl_in[HH * KPAD_IN];
__device__ __nv_bfloat16 g_wth[16 * HH * HH];
__device__ __nv_bfloat16 g_wtl[16 * HH * HH];

// ===================== small helpers ========================================
__device__ __forceinline__ uint32_t smem_u32(const void* p) {
    uint32_t a;
    asm("{ .reg .u64 t; cvta.to.shared.u64 t, %1; cvt.u32.u64 %0, t; }" : "=r"(a) : "l"(p));
    return a;
}

// 64B-row swizzle: XOR 16B-chunk index bits[5:4] with row bits (offset bits[8:7])
__device__ __forceinline__ uint32_t swz64(uint32_t o) { return o ^ ((o >> 3) & 0x30); }

__device__ __forceinline__ void bsplit(float v, __nv_bfloat16& h, __nv_bfloat16& l) {
    h = __float2bfloat16(v);
    l = __float2bfloat16(v - __bfloat162float(h));
}

__device__ __forceinline__ void ldsm4(uint32_t* r, uint32_t addr) {
    asm volatile("ldmatrix.sync.aligned.m8n8.x4.shared.b16 {%0,%1,%2,%3}, [%4];"
                 : "=r"(r[0]), "=r"(r[1]), "=r"(r[2]), "=r"(r[3]) : "r"(addr));
}

__device__ __forceinline__ void mma16816(float* d, const uint32_t* a, const uint32_t* b) {
    asm volatile(
        "mma.sync.aligned.m16n8k16.row.col.f32.bf16.bf16.f32 "
        "{%0,%1,%2,%3}, {%4,%5,%6,%7}, {%8,%9}, {%0,%1,%2,%3};"
        : "+f"(d[0]), "+f"(d[1]), "+f"(d[2]), "+f"(d[3])
        : "r"(a[0]), "r"(a[1]), "r"(a[2]), "r"(a[3]), "r"(b[0]), "r"(b[1]));
}

// ===================== CSR build ============================================
__global__ void zero_cnt_kernel() { g_cnt[blockIdx.x * blockDim.x + threadIdx.x] = 0; }

__global__ void hist_kernel(const int* __restrict__ dst) {
    int e = blockIdx.x * blockDim.x + threadIdx.x;
    atomicAdd(&g_cnt[dst[e]], 1);
}

__global__ void scan_kernel() {
    __shared__ int ssum[1024];
    int t = threadIdx.x;
    int base = t * 32;
    int local[32];
    int s = 0;
#pragma unroll
    for (int i = 0; i < 32; i++) { local[i] = s; s += g_cnt[base + i]; }
    ssum[t] = s;
    __syncthreads();
    for (int off = 1; off < 1024; off <<= 1) {
        int v = (t >= off) ? ssum[t - off] : 0;
        __syncthreads();
        ssum[t] += v;
        __syncthreads();
    }
    int offBase = (t == 0) ? 0 : ssum[t - 1];
#pragma unroll
    for (int i = 0; i < 32; i++) g_rowptr[base + i] = offBase + local[i];
    if (t == 1023) g_rowptr[NN] = offBase + s;
}

__global__ void init_cursor_kernel() {
    int i = blockIdx.x * blockDim.x + threadIdx.x;
    g_cursor[i] = g_rowptr[i];
}

__global__ void fill_kernel(const int* __restrict__ dst) {
    int e = blockIdx.x * blockDim.x + threadIdx.x;
    int p = atomicAdd(&g_cursor[dst[e]], 1);
    g_eids[p] = e;
}

__global__ void sort_kernel() {
    int n = blockIdx.x * blockDim.x + threadIdx.x;
    int lo = g_rowptr[n], hi = g_rowptr[n + 1];
    for (int i = lo + 1; i < hi; i++) {
        int key = g_eids[i];
        int j = i - 1;
        while (j >= lo && g_eids[j] > key) { g_eids[j + 1] = g_eids[j]; j--; }
        g_eids[j + 1] = key;
    }
}

// ===================== operand conversions ==================================
__global__ void convert_x_kernel(const float* __restrict__ x) {
    int idx = blockIdx.x * blockDim.x + threadIdx.x;   // over NN*KPAD_IN
    int r = idx / KPAD_IN, c = idx - r * KPAD_IN;
    float v = (c < IND) ? x[(size_t)r * IND + c] : 0.f;
    bsplit(v, g_xh[idx], g_xl[idx]);
}

__global__ void convert_win_kernel(const float* __restrict__ W) {  // [IND][HH] -> [HH][KPAD_IN]^T
    int idx = blockIdx.x * blockDim.x + threadIdx.x;   // over HH*KPAD_IN
    int n = idx / KPAD_IN, k = idx - n * KPAD_IN;
    float v = (k < IND) ? W[(size_t)k * HH + n] : 0.f;
    bsplit(v, g_wth_in[idx], g_wtl_in[idx]);
}

__global__ void convert_wqkvs_kernel(const float* __restrict__ Wq, const float* __restrict__ Wk,
                                     const float* __restrict__ Wv, const float* __restrict__ Ws) {
    int s = blockIdx.y;                  // slot 0..15: layer*4 + {q,k,v,skip}
    int layer = s >> 2, t = s & 3;
    const float* W = (t == 0 ? Wq : t == 1 ? Wk : t == 2 ? Wv : Ws) + (size_t)layer * HH * HH;
    int idx = blockIdx.x * blockDim.x + threadIdx.x;   // over HH*HH
    int n = idx >> 8, k = idx & 255;
    float v = W[k * HH + n];
    size_t o = (size_t)s * HH * HH + idx;               // [n][k] row-major
    bsplit(v, g_wth[o], g_wtl[o]);
}

// ===================== per-layer precompute =================================
__global__ void prep_layer_kernel(const float* __restrict__ W_ep,
                                  const float* __restrict__ b_ep,
                                  const float* __restrict__ We,
                                  const float* __restrict__ Wbeta) {
    int j = threadIdx.x;
    float m0 = 0.f, m1 = 0.f, m2 = 0.f, m3 = 0.f, bb = 0.f;
    for (int c = 0; c < HH; c++) {
        float w = We[c * HH + j];
        m0 += W_ep[c] * w;
        m1 += W_ep[HH + c] * w;
        m2 += W_ep[2 * HH + c] * w;
        m3 += W_ep[3 * HH + c] * w;
        bb += b_ep[c] * w;
    }
    g_Me[j] = m0; g_Me[HH + j] = m1; g_Me[2 * HH + j] = m2; g_Me[3 * HH + j] = m3;
    g_be[j] = bb;
    g_wbo[j] = Wbeta[j] + Wbeta[2 * HH + j];
    g_wbx[j] = Wbeta[HH + j] - Wbeta[2 * HH + j];
}

// ===================== bf16-split MMA GEMM (mma.sync path) ==================
// C[rowBase:+128, colBase:+128] = A[.., 0:K] @ W[0:K, ..] + bias
// A: bf16 hi/lo row-major [M x ldA]. W: bf16 hi/lo TRANSPOSED [256(N) x ldA].
// Block: 256 thr (8 warps: 4 m x 2 n). Warp tile 32(m) x 64(n).
// SMEM: Ah 8K | Al 8K | Bh 8K | Bl 8K  (rows 64B, swz64).
__device__ __forceinline__ void gemm_body(
    const __nv_bfloat16* __restrict__ Ah, const __nv_bfloat16* __restrict__ Al,
    int ldA, int kChunks,
    const __nv_bfloat16* __restrict__ Bh, const __nv_bfloat16* __restrict__ Bl,
    const float* __restrict__ bias, float* __restrict__ C,
    __nv_bfloat16* Ch, __nv_bfloat16* Cl) {
    __shared__ __align__(128) char smem[32768];
    const uint32_t SA_H = 0, SA_L = 8192, SB_H = 16384, SB_L = 24576;
    uint32_t sm = smem_u32(smem);

    int tid = threadIdx.x;
    int lane = tid & 31, wid = tid >> 5;
    int warpM = wid & 3, warpN = wid >> 2;
    int rowBase = blockIdx.x * 128;
    int colBase = blockIdx.y * 128;

    // ldmatrix per-thread row/k pieces
    int lr = lane & 7;
    int rowA0 = warpM * 32 + lr + ((lane & 8) ? 8 : 0);   // m-frag 0; +16 for frag 1
    int kA16  = (lane & 16) ? 16 : 0;
    int rowB0 = warpN * 64 + lr + ((lane & 16) ? 8 : 0);  // n16-group 0; +16*g
    int kB16  = (lane & 8) ? 16 : 0;

    float acc[2][8][4];
#pragma unroll
    for (int a = 0; a < 2; a++)
#pragma unroll
        for (int b = 0; b < 8; b++)
#pragma unroll
            for (int c = 0; c < 4; c++) acc[a][b][c] = 0.f;

    for (int ch = 0; ch < kChunks; ch++) {
        int k0 = ch * 32;
        // fill A tiles: 128 rows x 32 cols bf16 (hi,lo) = 512 uint4 each
#pragma unroll
        for (int i = 0; i < 2; i++) {
            int idx = i * 256 + tid;          // 0..511
            int r = idx >> 2, v = idx & 3;
            size_t go = (size_t)(rowBase + r) * ldA + k0 + v * 8;
            uint32_t so = swz64((uint32_t)(r * 64 + v * 16));
            *(uint4*)(smem + SA_H + so) = *(const uint4*)(Ah + go);
            *(uint4*)(smem + SA_L + so) = *(const uint4*)(Al + go);
        }
        // fill B tiles: rows n (colBase..+127) x 32 k
#pragma unroll
        for (int i = 0; i < 2; i++) {
            int idx = i * 256 + tid;
            int r = idx >> 2, v = idx & 3;
            size_t go = (size_t)(colBase + r) * ldA + k0 + v * 8;
            uint32_t so = swz64((uint32_t)(r * 64 + v * 16));
            *(uint4*)(smem + SB_H + so) = *(const uint4*)(Bh + go);
            *(uint4*)(smem + SB_L + so) = *(const uint4*)(Bl + go);
        }
        __syncthreads();
#pragma unroll
        for (int ks = 0; ks < 2; ks++) {
            int kbA = ks * 32 + kA16;
            int kbB = ks * 32 + kB16;
            uint32_t a_h[2][4], a_l[2][4];
            ldsm4(a_h[0], sm + SA_H + swz64((uint32_t)(rowA0 * 64 + kbA)));
            ldsm4(a_h[1], sm + SA_H + swz64((uint32_t)((rowA0 + 16) * 64 + kbA)));
            ldsm4(a_l[0], sm + SA_L + swz64((uint32_t)(rowA0 * 64 + kbA)));
            ldsm4(a_l[1], sm + SA_L + swz64((uint32_t)((rowA0 + 16) * 64 + kbA)));
#pragma unroll
            for (int g = 0; g < 4; g++) {
                uint32_t b_h[4], b_l[4];
                uint32_t boff = swz64((uint32_t)((rowB0 + g * 16) * 64 + kbB));
                ldsm4(b_h, sm + SB_H + boff);
                ldsm4(b_l, sm + SB_L + boff);
#pragma unroll
                for (int mf = 0; mf < 2; mf++) {
                    mma16816(acc[mf][2 * g],     a_h[mf], b_h);
                    mma16816(acc[mf][2 * g],     a_h[mf], b_l);
                    mma16816(acc[mf][2 * g],     a_l[mf], b_h);
                    mma16816(acc[mf][2 * g + 1], a_h[mf], b_h + 2);
                    mma16816(acc[mf][2 * g + 1], a_h[mf], b_l + 2);
                    mma16816(acc[mf][2 * g + 1], a_l[mf], b_h + 2);
                }
            }
        }
        __syncthreads();
    }

    // epilogue
    int gid = lane >> 2, qid = lane & 3;
#pragma unroll
    for (int mf = 0; mf < 2; mf++) {
#pragma unroll
        for (int nf = 0; nf < 8; nf++) {
            int col = colBase + warpN * 64 + nf * 8 + qid * 2;
            float b0 = bias[col], b1 = bias[col + 1];
            int r0 = rowBase + warpM * 32 + mf * 16 + gid;
            float v00 = acc[mf][nf][0] + b0, v01 = acc[mf][nf][1] + b1;
            float v10 = acc[mf][nf][2] + b0, v11 = acc[mf][nf][3] + b1;
            *(float2*)(C + (size_t)r0 * HH + col)       = make_float2(v00, v01);
            *(float2*)(C + (size_t)(r0 + 8) * HH + col) = make_float2(v10, v11);
            if (Ch) {
                size_t o0 = (size_t)r0 * HH + col, o1 = (size_t)(r0 + 8) * HH + col;
                bsplit(v00, Ch[o0], Cl[o0]); bsplit(v01, Ch[o0 + 1], Cl[o0 + 1]);
                bsplit(v10, Ch[o1], Cl[o1]); bsplit(v11, Ch[o1 + 1], Cl[o1 + 1]);
            }
        }
    }
}

__global__ void __launch_bounds__(256)
gemm_in_tc(const float* __restrict__ bias) {
    gemm_body(g_xh, g_xl, KPAD_IN, KPAD_IN / 32, g_wth_in, g_wtl_in, bias, g_h, g_hh, g_hl);
}

__global__ void __launch_bounds__(256)
gemm_qkvs_tc(const float* __restrict__ bq, const float* __restrict__ bk,
             const float* __restrict__ bv, const float* __restrict__ bs, int layer) {
    int z = blockIdx.z;
    const float* bias;
    float* C;
    switch (z) {
        case 0:  bias = bq; C = g_q;  break;
        case 1:  bias = bk; C = g_k;  break;
        case 2:  bias = bv; C = g_v;  break;
        default: bias = bs; C = g_xr; break;
    }
    size_t slot = (size_t)(layer * 4 + z) * HH * HH;
    gemm_body(g_hh, g_hl, HH, HH / 32, g_wth + slot, g_wtl + slot, bias, C,
              (__nv_bfloat16*)0, (__nv_bfloat16*)0);
}

// ===================== attention: warp per node, online softmax =============
__global__ void __launch_bounds__(128)
attn_kernel(const float* __restrict__ eattr, const int* __restrict__ src) {
    __shared__ float sMe[4 * HH];
    __shared__ float sbe[HH];
    for (int i = threadIdx.x; i < 4 * HH; i += 128) sMe[i] = g_Me[i];
    for (int i = threadIdx.x; i < HH; i += 128) sbe[i] = g_be[i];
    __syncthreads();

    int n = blockIdx.x * 4 + (threadIdx.x >> 5);
    int lane = threadIdx.x & 31;
    int dim0 = lane * 8;

    const float4* q4 = (const float4*)(g_q + (size_t)n * HH + dim0);
    float4 qa = q4[0], qb = q4[1];
    float ql[8] = {qa.x, qa.y, qa.z, qa.w, qb.x, qb.y, qb.z, qb.w};

    float m = -INFINITY, lsum = 0.f;
    float acc[8] = {0.f, 0.f, 0.f, 0.f, 0.f, 0.f, 0.f, 0.f};

    int e0 = g_rowptr[n], e1 = g_rowptr[n + 1];
    for (int ii = e0; ii < e1; ii++) {
        int eid = g_eids[ii];
        int s = src[eid];
        float a0 = eattr[eid * 4 + 0], a1 = eattr[eid * 4 + 1];
        float a2 = eattr[eid * 4 + 2], a3 = eattr[eid * 4 + 3];
        float ed[8];
#pragma unroll
        for (int d = 0; d < 8; d++) {
            int dd = dim0 + d;
            ed[d] = sbe[dd] + a0 * sMe[dd] + a1 * sMe[HH + dd]
                            + a2 * sMe[2 * HH + dd] + a3 * sMe[3 * HH + dd];
        }
        const float4* k4 = (const float4*)(g_k + (size_t)s * HH + dim0);
        float4 ka = k4[0], kb = k4[1];
        float kj[8] = {ka.x, ka.y, ka.z, ka.w, kb.x, kb.y, kb.z, kb.w};
        float part = 0.f;
#pragma unroll
        for (int d = 0; d < 8; d++) part += ql[d] * (kj[d] + ed[d]);
        part += __shfl_xor_sync(0xffffffffu, part, 1);
        part += __shfl_xor_sync(0xffffffffu, part, 2);
        float alpha = part * 0.17677669529663687f;  // 1/sqrt(32)

        float mnew = fmaxf(m, alpha);
        float scale = __expf(m - mnew);
        float w = __expf(alpha - mnew);
        lsum = lsum * scale + w;

        const float4* v4 = (const float4*)(g_v + (size_t)s * HH + dim0);
        float4 va = v4[0], vb = v4[1];
        float vj[8] = {va.x, va.y, va.z, va.w, vb.x, vb.y, vb.z, vb.w};
#pragma unroll
        for (int d = 0; d < 8; d++) acc[d] = acc[d] * scale + w * (vj[d] + ed[d]);
        m = mnew;
    }
    float inv = 1.f / (lsum + 1e-16f);
    float4* o = (float4*)(g_att + (size_t)n * HH + dim0);
    o[0] = make_float4(acc[0] * inv, acc[1] * inv, acc[2] * inv, acc[3] * inv);
    o[1] = make_float4(acc[4] * inv, acc[5] * inv, acc[6] * inv, acc[7] * inv);
}

// ===================== fused beta + LN + ReLU + residual (+bf16 split) ======
__device__ __forceinline__ float warpSum(float x) {
    x += __shfl_xor_sync(0xffffffffu, x, 16);
    x += __shfl_xor_sync(0xffffffffu, x, 8);
    x += __shfl_xor_sync(0xffffffffu, x, 4);
    x += __shfl_xor_sync(0xffffffffu, x, 2);
    x += __shfl_xor_sync(0xffffffffu, x, 1);
    return x;
}

__global__ void __launch_bounds__(128)
fuse_kernel(const float* __restrict__ lng, const float* __restrict__ lnb) {
    int n = blockIdx.x * 4 + (threadIdx.x >> 5);
    int lane = threadIdx.x & 31;
    int dim0 = lane * 8;
    size_t base = (size_t)n * HH + dim0;

    const float4* o4 = (const float4*)(g_att + base);
    const float4* x4 = (const float4*)(g_xr + base);
    float4 oa = o4[0], ob = o4[1], xa = x4[0], xb = x4[1];
    float o[8] = {oa.x, oa.y, oa.z, oa.w, ob.x, ob.y, ob.z, ob.w};
    float xr[8] = {xa.x, xa.y, xa.z, xa.w, xb.x, xb.y, xb.z, xb.w};

    float part = 0.f;
#pragma unroll
    for (int d = 0; d < 8; d++)
        part += o[d] * g_wbo[dim0 + d] + xr[d] * g_wbx[dim0 + d];
    part = warpSum(part);
    float beta = 1.f / (1.f + __expf(-part));

    float hn[8];
    float ssum = 0.f;
#pragma unroll
    for (int d = 0; d < 8; d++) { hn[d] = beta * xr[d] + (1.f - beta) * o[d]; ssum += hn[d]; }
    float mu = warpSum(ssum) * (1.f / HH);
    float sv = 0.f;
#pragma unroll
    for (int d = 0; d < 8; d++) { float t = hn[d] - mu; sv += t * t; }
    float var = warpSum(sv) * (1.f / HH);
    float inv = rsqrtf(var + 1e-5f);
#pragma unroll
    for (int d = 0; d < 8; d++) {
        float y = (hn[d] - mu) * inv * lng[dim0 + d] + lnb[dim0 + d];
        float nv = fmaxf(y, 0.f) + g_h[base + d];
        g_h[base + d] = nv;
        bsplit(nv, g_hh[base + d], g_hl[base + d]);
    }
}

// ===================== pooling + head ======================================
__global__ void __launch_bounds__(256)
pool_head_kernel(const int* __restrict__ batch,
                 const float* __restrict__ Wc1, const float* __restrict__ bc1,
                 const float* __restrict__ lncg, const float* __restrict__ lncb,
                 const float* __restrict__ Wc2, const float* __restrict__ bc2,
                 const float* __restrict__ Wc3, const float* __restrict__ bc3,
                 float* __restrict__ out) {
    int g = blockIdx.x, tid = threadIdx.x;
    __shared__ int s_lo, s_hi;
    if (tid == 0) {
        int lo = 0, hi = NN;
        while (lo < hi) { int mid = (lo + hi) >> 1; if (batch[mid] < g) lo = mid + 1; else hi = mid; }
        s_lo = lo;
        lo = 0; hi = NN;
        while (lo < hi) { int mid = (lo + hi) >> 1; if (batch[mid] < g + 1) lo = mid + 1; else hi = mid; }
        s_hi = lo;
    }
    __syncthreads();
    int lo = s_lo, hi = s_hi;
    float sum = 0.f;
    for (int n = lo; n < hi; n++) sum += g_h[(size_t)n * HH + tid];
    __shared__ float ge[2 * HH];
    float cnt = (float)((hi - lo) > 1 ? (hi - lo) : 1);
    ge[tid] = sum / cnt;
    ge[HH + tid] = sum;
    __syncthreads();

    float c1 = bc1[tid];
    for (int k = 0; k < 2 * HH; k++) c1 += ge[k] * Wc1[k * HH + tid];

    __shared__ float red[HH];
    red[tid] = c1; __syncthreads();
    for (int s = HH / 2; s > 0; s >>= 1) { if (tid < s) red[tid] += red[tid + s]; __syncthreads(); }
    float mu = red[0] * (1.f / HH);
    __syncthreads();
    float t = c1 - mu;
    red[tid] = t * t; __syncthreads();
    for (int s = HH / 2; s > 0; s >>= 1) { if (tid < s) red[tid] += red[tid + s]; __syncthreads(); }
    float var = red[0] * (1.f / HH);
    __syncthreads();
    float y = (c1 - mu) * rsqrtf(var + 1e-5f) * lncg[tid] + lncb[tid];
    float c1r = fmaxf(y, 0.f);

    __shared__ float s1[HH];
    s1[tid] = c1r; __syncthreads();
    __shared__ float s2[HH / 2];
    if (tid < HH / 2) {
        float c2 = bc2[tid];
        for (int k = 0; k < HH; k++) c2 += s1[k] * Wc2[k * (HH / 2) + tid];
        s2[tid] = fmaxf(c2, 0.f);
    }
    __syncthreads();
    if (tid < HH / 2) red[tid] = s2[tid] * Wc3[tid];
    __syncthreads();
    for (int s = HH / 4; s > 0; s >>= 1) { if (tid < s) red[tid] += red[tid + s]; __syncthreads(); }
    if (tid == 0) out[g] = red[0] + bc3[0];
}

// ===================== host launcher =======================================
extern "C" void kernel_launch(void* const* d_in, const int* in_sizes, int n_in,
                              void* d_out_, int out_size) {
    const float* x     = (const float*)d_in[0];
    const int*   ei    = (const int*)  d_in[1];
    const float* eattr = (const float*)d_in[2];
    const int*   batch = (const int*)  d_in[3];
    const float* W_in  = (const float*)d_in[4];
    const float* b_in  = (const float*)d_in[5];
    const float* W_ep  = (const float*)d_in[6];
    const float* b_ep  = (const float*)d_in[7];
    const float* Wq    = (const float*)d_in[8];
    const float* bq    = (const float*)d_in[9];
    const float* Wk    = (const float*)d_in[10];
    const float* bk    = (const float*)d_in[11];
    const float* Wv    = (const float*)d_in[12];
    const float* bv    = (const float*)d_in[13];
    const float* We    = (const float*)d_in[14];
    const float* Wskip = (const float*)d_in[15];
    const float* bskip = (const float*)d_in[16];
    const float* Wbeta = (const float*)d_in[17];
    const float* lng   = (const float*)d_in[18];
    const float* lnb   = (const float*)d_in[19];
    const float* Wc1   = (const float*)d_in[20];
    const float* bc1   = (const float*)d_in[21];
    const float* lncg  = (const float*)d_in[22];
    const float* lncb  = (const float*)d_in[23];
    const float* Wc2   = (const float*)d_in[24];
    const float* bc2   = (const float*)d_in[25];
    const float* Wc3   = (const float*)d_in[26];
    const float* bc3   = (const float*)d_in[27];
    float* out = (float*)d_out_;

    const int* src = ei;        // edge_index[0]
    const int* dst = ei + EE;   // edge_index[1]

    // CSR build (deterministic after per-node sort)
    zero_cnt_kernel<<<NN / 256, 256>>>();
    hist_kernel<<<EE / 256, 256>>>(dst);
    scan_kernel<<<1, 1024>>>();
    init_cursor_kernel<<<NN / 256, 256>>>();
    fill_kernel<<<EE / 256, 256>>>(dst);
    sort_kernel<<<NN / 256, 256>>>();

    // operand conversions (bf16 hi/lo splits, weight transposes)
    convert_x_kernel<<<(NN * KPAD_IN) / 256, 256>>>(x);
    convert_win_kernel<<<(HH * KPAD_IN) / 256, 256>>>(W_in);
    convert_wqkvs_kernel<<<dim3((HH * HH) / 256, 16), 256>>>(Wq, Wk, Wv, Wskip);

    // input projection (tensor core, split bf16)
    gemm_in_tc<<<dim3(NN / 128, 2), 256>>>(b_in);

    for (int i = 0; i < LL; i++) {
        prep_layer_kernel<<<1, HH>>>(W_ep, b_ep, We + i * HH * HH, Wbeta + i * 3 * HH);
        gemm_qkvs_tc<<<dim3(NN / 128, 2, 4), 256>>>(
            bq + i * HH, bk + i * HH, bv + i * HH, bskip + i * HH, i);
        attn_kernel<<<NN / 4, 128>>>(eattr, src);
        fuse_kernel<<<NN / 4, 128>>>(lng + i * HH, lnb + i * HH);
    }

    pool_head_kernel<<<GG, 256>>>(batch, Wc1, bc1, lncg, lncb, Wc2, bc2, Wc3, bc3, out);
}